// round 2
// baseline (speedup 1.0000x reference)
#include <cuda_runtime.h>

// Problem constants
#define NBQ   4
#define NHQ   16
#define NS    4096
#define ND    64          // head dim
#define NF    9
#define NDIM  128         // 2*ND (router input dim)
#define NBH   (NBQ*NHQ)   // 64

#define SCHUNKS 16
#define SCHUNK  (NS/SCHUNKS)  // 256
#define TS      64            // s-tile (and token-tile) size

// Deterministic partial buffers (device globals: no allocation allowed)
__device__ float g_KVpart[SCHUNKS * NBH * ND * ND];  // ~16.8 MB
__device__ float g_KV[NBH * ND * ND];                // 1 MB

typedef unsigned long long u64;

// ---- packed f32x2 helpers (sm_103a FFMA2 path) ----
__device__ __forceinline__ u64 pack2(float x, float y) {
    u64 r; asm("mov.b64 %0, {%1, %2};" : "=l"(r) : "f"(x), "f"(y)); return r;
}
__device__ __forceinline__ void unpack2(u64 v, float& x, float& y) {
    asm("mov.b64 {%0, %1}, %2;" : "=f"(x), "=f"(y) : "l"(v));
}
__device__ __forceinline__ u64 ffma2(u64 a, u64 b, u64 c) {
    u64 d; asm("fma.rn.f32x2 %0, %1, %2, %3;" : "=l"(d) : "l"(a), "l"(b), "l"(c));
    return d;
}

// Stage one 64x64 tile of X_diff = X - lambda*X' into sXd (and optionally V into sV).
// Fast path (uniform lambdas): single fused global->smem pass, no routing.
// General path: stage X, compute per-row router scores (concat[X,X'] @ W^T),
// argmax -> lambda, then apply. Caller must __syncthreads() after return.
template <bool WITH_V>
__device__ __forceinline__ void stage_tile(
    const float* __restrict__ Xt, const float* __restrict__ Xp,
    const float* __restrict__ Vg,
    long tb, float* sXd, float* sV,
    const float* sW, const float* sLam, float* sLamRow,
    bool uniform, float lam0, int tid)
{
    if (uniform) {
        #pragma unroll
        for (int idx = tid; idx < TS * ND / 4; idx += 256) {
            float4 a = *(const float4*)(Xt + tb + idx * 4);
            float4 b = *(const float4*)(Xp + tb + idx * 4);
            float4 r;
            r.x = a.x - lam0 * b.x;  r.y = a.y - lam0 * b.y;
            r.z = a.z - lam0 * b.z;  r.w = a.w - lam0 * b.w;
            *(float4*)(sXd + idx * 4) = r;
            if (WITH_V)
                *(float4*)(sV + idx * 4) = *(const float4*)(Vg + tb + idx * 4);
        }
    } else {
        // stage raw X (and V)
        #pragma unroll
        for (int idx = tid; idx < TS * ND / 4; idx += 256) {
            *(float4*)(sXd + idx * 4) = *(const float4*)(Xt + tb + idx * 4);
            if (WITH_V)
                *(float4*)(sV + idx * 4) = *(const float4*)(Vg + tb + idx * 4);
        }
        __syncthreads();
        // routing: 4 threads per row, each covers 32 of the 128 concat dims
        const int g = tid >> 2, q = tid & 3;
        const float* xptr = (q < 2) ? (sXd + g * ND + 32 * q)
                                    : (Xp + tb + (long)g * ND + 32 * (q - 2));
        float sc[NF];
        #pragma unroll
        for (int n = 0; n < NF; n++) sc[n] = 0.f;
        #pragma unroll
        for (int e4 = 0; e4 < 8; e4++) {
            float4 xv = *(const float4*)(xptr + 4 * e4);
            #pragma unroll
            for (int n = 0; n < NF; n++) {
                float4 wv = *(const float4*)(sW + n * NDIM + 32 * q + 4 * e4);
                sc[n] += xv.x * wv.x + xv.y * wv.y + xv.z * wv.z + xv.w * wv.w;
            }
        }
        #pragma unroll
        for (int n = 0; n < NF; n++) {
            sc[n] += __shfl_xor_sync(0xffffffffu, sc[n], 1);
            sc[n] += __shfl_xor_sync(0xffffffffu, sc[n], 2);
        }
        int best = 0;
        #pragma unroll
        for (int n = 1; n < NF; n++) if (sc[n] > sc[best]) best = n;
        // broadcast from group leader so all 4 lanes agree bitwise
        best = __shfl_sync(0xffffffffu, best, (tid & 31) & ~3);
        if (q == 0) sLamRow[g] = sLam[best];
        __syncthreads();
        // apply: Xd = X - lambda[row] * X'
        #pragma unroll
        for (int idx = tid; idx < TS * ND / 4; idx += 256) {
            int row = idx >> 4;
            float l = sLamRow[row];
            float4 b = *(const float4*)(Xp + tb + idx * 4);
            float4 a = *(float4*)(sXd + idx * 4);
            a.x -= l * b.x;  a.y -= l * b.y;
            a.z -= l * b.z;  a.w -= l * b.w;
            *(float4*)(sXd + idx * 4) = a;
        }
    }
}

// Phase A: per (chunk, bh), accumulate partial KV[d][e] = sum_s Kd[s,d] * V[s,e]
__global__ void __launch_bounds__(256) kv_kernel(
    const float* __restrict__ Kt, const float* __restrict__ Kp,
    const float* __restrict__ Vg, const float* __restrict__ lambdas,
    const float* __restrict__ Wk)
{
    __shared__ float sKd[TS * ND];
    __shared__ float sV[TS * ND];
    __shared__ float sW[NF * NDIM];
    __shared__ float sLam[NF];
    __shared__ float sLamRow[TS];
    __shared__ int   sUni;

    const int tid = threadIdx.x;
    const int chunk = blockIdx.x, bh = blockIdx.y;

    if (tid < NF) sLam[tid] = lambdas[tid];
    for (int idx = tid; idx < NF * NDIM; idx += 256) sW[idx] = Wk[idx];
    __syncthreads();
    if (tid == 0) {
        float mn = sLam[0], mx = sLam[0];
        #pragma unroll
        for (int n = 1; n < NF; n++) { mn = fminf(mn, sLam[n]); mx = fmaxf(mx, sLam[n]); }
        sUni = (mn == mx) ? 1 : 0;
    }
    __syncthreads();
    const bool uniform = (sUni != 0);
    const float lam0 = sLam[0];

    const int i = tid >> 4, j = tid & 15;  // 16x16 thread tile -> 4x4 outputs each
    u64 acc[4][2];
    #pragma unroll
    for (int a = 0; a < 4; a++) { acc[a][0] = 0ull; acc[a][1] = 0ull; }

    const long base = ((long)bh * NS + (long)chunk * SCHUNK) * ND;

    for (int t = 0; t < SCHUNK / TS; t++) {
        const long tb = base + (long)t * TS * ND;
        stage_tile<true>(Kt, Kp, Vg, tb, sKd, sV, sW, sLam, sLamRow, uniform, lam0, tid);
        __syncthreads();

        const float* kr = sKd + 4 * i;
        const float* vr = sV + 4 * j;
        #pragma unroll 4
        for (int s = 0; s < TS; s++) {
            float4 k4 = *(const float4*)(kr + s * ND);
            float4 v4 = *(const float4*)(vr + s * ND);
            u64 v01 = pack2(v4.x, v4.y), v23 = pack2(v4.z, v4.w);
            u64 k0 = pack2(k4.x, k4.x), k1 = pack2(k4.y, k4.y);
            u64 k2 = pack2(k4.z, k4.z), k3 = pack2(k4.w, k4.w);
            acc[0][0] = ffma2(k0, v01, acc[0][0]); acc[0][1] = ffma2(k0, v23, acc[0][1]);
            acc[1][0] = ffma2(k1, v01, acc[1][0]); acc[1][1] = ffma2(k1, v23, acc[1][1]);
            acc[2][0] = ffma2(k2, v01, acc[2][0]); acc[2][1] = ffma2(k2, v23, acc[2][1]);
            acc[3][0] = ffma2(k3, v01, acc[3][0]); acc[3][1] = ffma2(k3, v23, acc[3][1]);
        }
        __syncthreads();
    }

    float* op = g_KVpart + ((long)chunk * NBH + bh) * (ND * ND) + (4 * i) * ND + 4 * j;
    #pragma unroll
    for (int di = 0; di < 4; di++) {
        float4 r;
        unpack2(acc[di][0], r.x, r.y);
        unpack2(acc[di][1], r.z, r.w);
        *(float4*)(op + di * ND) = r;
    }
}

// Reduce the SCHUNKS partials -> g_KV (deterministic)
__global__ void __launch_bounds__(256) reduce_kernel()
{
    const int idx = blockIdx.x * 256 + threadIdx.x;  // over NBH*ND*ND = 262144
    float s = 0.f;
    #pragma unroll
    for (int c = 0; c < SCHUNKS; c++)
        s += g_KVpart[(long)c * (NBH * ND * ND) + idx];
    g_KV[idx] = s;
}

// Phase B: O[s][e] = sum_d Qd[s,d] * KV[d][e], one 64-token tile per block
__global__ void __launch_bounds__(256) out_kernel(
    const float* __restrict__ Qt, const float* __restrict__ Qp,
    const float* __restrict__ lambdas, const float* __restrict__ Wq,
    float* __restrict__ O)
{
    __shared__ float sQd[TS * ND];
    __shared__ float sKV[ND * ND];
    __shared__ float sW[NF * NDIM];
    __shared__ float sLam[NF];
    __shared__ float sLamRow[TS];
    __shared__ int   sUni;

    const int tid = threadIdx.x;
    const int st = blockIdx.x, bh = blockIdx.y;

    if (tid < NF) sLam[tid] = lambdas[tid];
    for (int idx = tid; idx < NF * NDIM; idx += 256) sW[idx] = Wq[idx];
    // load this head's KV into smem
    {
        const float4* kvsrc = (const float4*)(g_KV + (long)bh * ND * ND);
        #pragma unroll
        for (int idx = tid; idx < ND * ND / 4; idx += 256)
            ((float4*)sKV)[idx] = kvsrc[idx];
    }
    __syncthreads();
    if (tid == 0) {
        float mn = sLam[0], mx = sLam[0];
        #pragma unroll
        for (int n = 1; n < NF; n++) { mn = fminf(mn, sLam[n]); mx = fmaxf(mx, sLam[n]); }
        sUni = (mn == mx) ? 1 : 0;
    }
    __syncthreads();
    const bool uniform = (sUni != 0);
    const float lam0 = sLam[0];

    const long tb = ((long)bh * NS + (long)st * TS) * ND;
    stage_tile<false>(Qt, Qp, nullptr, tb, sQd, nullptr, sW, sLam, sLamRow,
                      uniform, lam0, tid);
    __syncthreads();

    const int i = tid >> 4, j = tid & 15;  // rows 4i..4i+3 (tokens), cols 4j..4j+3 (e)
    u64 acc[4][2];
    #pragma unroll
    for (int a = 0; a < 4; a++) { acc[a][0] = 0ull; acc[a][1] = 0ull; }

    #pragma unroll 4
    for (int d = 0; d < ND; d++) {
        float4 kv4 = *(const float4*)(sKV + d * ND + 4 * j);
        u64 v01 = pack2(kv4.x, kv4.y), v23 = pack2(kv4.z, kv4.w);
        #pragma unroll
        for (int di = 0; di < 4; di++) {
            float qv = sQd[(4 * i + di) * ND + d];
            u64 qq = pack2(qv, qv);
            acc[di][0] = ffma2(qq, v01, acc[di][0]);
            acc[di][1] = ffma2(qq, v23, acc[di][1]);
        }
    }

    float* op = O + tb + (4 * i) * ND + 4 * j;
    #pragma unroll
    for (int di = 0; di < 4; di++) {
        float4 r;
        unpack2(acc[di][0], r.x, r.y);
        unpack2(acc[di][1], r.z, r.w);
        *(float4*)(op + di * ND) = r;
    }
}

extern "C" void kernel_launch(void* const* d_in, const int* in_sizes, int n_in,
                              void* d_out, int out_size)
{
    const float* Qt  = (const float*)d_in[0];
    const float* Qp  = (const float*)d_in[1];
    const float* Kt  = (const float*)d_in[2];
    const float* Kp  = (const float*)d_in[3];
    const float* Vg  = (const float*)d_in[4];
    const float* lam = (const float*)d_in[5];
    const float* Wq  = (const float*)d_in[6];
    const float* Wk  = (const float*)d_in[7];
    float* O = (float*)d_out;

    kv_kernel<<<dim3(SCHUNKS, NBH), 256>>>(Kt, Kp, Vg, lam, Wk);
    reduce_kernel<<<(NBH * ND * ND) / 256, 256>>>();
    out_kernel<<<dim3(NS / TS, NBH), 256>>>(Qt, Qp, lam, Wq, O);
}

// round 7
// speedup vs baseline: 2.4244x; 2.4244x over previous
#include <cuda_runtime.h>
#include <cuda_bf16.h>
#include <cstdint>

#define NS    4096
#define ND    64
#define NF    9
#define NDIM  128
#define NBH   64
#define SCHUNKS 16
#define SCHUNK  256

__device__ float g_KVpart[SCHUNKS * NBH * ND * ND];
__device__ float g_KV[NBH * ND * ND];

typedef unsigned int u32;
typedef unsigned long long u64;

// ---------------- helpers ----------------
__device__ __forceinline__ u32 smem_u32(const void* p) {
    u32 a;
    asm("{ .reg .u64 t; cvta.to.shared.u64 t, %1; cvt.u32.u64 %0, t; }" : "=r"(a) : "l"(p));
    return a;
}

// Swizzled byte offset inside a [rows][64 bf16] tile (128B rows, 8 chunks of 16B,
// chunk ^= row&7). Conflict-free for both per-row stores and ldmatrix reads.
__device__ __forceinline__ u32 swoff(int row, int col) {
    return (u32)((row << 7) + ((((col >> 3) ^ row) & 7) << 4) + ((col & 7) << 1));
}

// pack two floats as bf16 hi parts + bf16 residual lo parts (x -> low half)
__device__ __forceinline__ void split2(float x, float y, u32& hi, u32& lo) {
    __nv_bfloat16 hx = __float2bfloat16_rn(x);
    __nv_bfloat16 hy = __float2bfloat16_rn(y);
    __nv_bfloat16 lx = __float2bfloat16_rn(x - __bfloat162float(hx));
    __nv_bfloat16 ly = __float2bfloat16_rn(y - __bfloat162float(hy));
    hi = (u32)__bfloat16_as_ushort(hx) | ((u32)__bfloat16_as_ushort(hy) << 16);
    lo = (u32)__bfloat16_as_ushort(lx) | ((u32)__bfloat16_as_ushort(ly) << 16);
}

__device__ __forceinline__ void ldsm_x4(u32 r[4], u32 addr) {
    asm volatile("ldmatrix.sync.aligned.m8n8.x4.shared.b16 {%0,%1,%2,%3}, [%4];"
                 : "=r"(r[0]), "=r"(r[1]), "=r"(r[2]), "=r"(r[3]) : "r"(addr));
}
__device__ __forceinline__ void ldsm_x2(u32& r0, u32& r1, u32 addr) {
    asm volatile("ldmatrix.sync.aligned.m8n8.x2.shared.b16 {%0,%1}, [%2];"
                 : "=r"(r0), "=r"(r1) : "r"(addr));
}
__device__ __forceinline__ void mma16816(float* c, const u32* a, u32 b0, u32 b1) {
    asm volatile("mma.sync.aligned.m16n8k16.row.col.f32.bf16.bf16.f32 "
                 "{%0,%1,%2,%3}, {%4,%5,%6,%7}, {%8,%9}, {%0,%1,%2,%3};"
                 : "+f"(c[0]), "+f"(c[1]), "+f"(c[2]), "+f"(c[3])
                 : "r"(a[0]), "r"(a[1]), "r"(a[2]), "r"(a[3]), "r"(b0), "r"(b1));
}

// -------- routing (general path), NTHR threads, `rows` rows starting at gmem tb --------
template <int NTHR>
__device__ __forceinline__ void route_rows(
    const float* __restrict__ Xt, const float* __restrict__ Xp, long tb,
    const float* sW, const float* sLam, float* sLamRow, int rows, int tid)
{
    const int RP = NTHR / 4;
    for (int r0 = 0; r0 < rows; r0 += RP) {
        const int g = r0 + (tid >> 2), q = tid & 3;
        const float* xptr = (q < 2) ? (Xt + tb + (long)g * ND + 32 * q)
                                    : (Xp + tb + (long)g * ND + 32 * (q - 2));
        float sc[NF];
        #pragma unroll
        for (int n = 0; n < NF; n++) sc[n] = 0.f;
        #pragma unroll
        for (int e4 = 0; e4 < 8; e4++) {
            float4 xv = *(const float4*)(xptr + 4 * e4);
            #pragma unroll
            for (int n = 0; n < NF; n++) {
                float4 wv = *(const float4*)(sW + n * NDIM + 32 * q + 4 * e4);
                sc[n] += xv.x * wv.x + xv.y * wv.y + xv.z * wv.z + xv.w * wv.w;
            }
        }
        #pragma unroll
        for (int n = 0; n < NF; n++) {
            sc[n] += __shfl_xor_sync(0xffffffffu, sc[n], 1);
            sc[n] += __shfl_xor_sync(0xffffffffu, sc[n], 2);
        }
        int best = 0;
        #pragma unroll
        for (int n = 1; n < NF; n++) if (sc[n] > sc[best]) best = n;
        best = __shfl_sync(0xffffffffu, best, (tid & 31) & ~3);
        if (q == 0) sLamRow[g] = sLam[best];
    }
}

// ==================== Phase A: KV partials via mma.sync ====================
// Per block (chunk, bh): out 64x64 (d x e), K = 256 s in 4 tiles of 64.
// smem: Kd as [d][s] (A, transposed), V as [e][s] (B), bf16 hi/lo, swizzled.
__global__ void __launch_bounds__(128) kv_tc(
    const float* __restrict__ Kt, const float* __restrict__ Kp,
    const float* __restrict__ Vg, const float* __restrict__ lambdas,
    const float* __restrict__ Wk)
{
    __shared__ char sKH[64 * 128], sKL[64 * 128], sVH[64 * 128], sVL[64 * 128];
    __shared__ float sW[NF * NDIM];
    __shared__ float sLam[NF];
    __shared__ float sLamRow[64];
    __shared__ int   sUni;

    const int tid = threadIdx.x;
    const int chunk = blockIdx.x, bh = blockIdx.y;

    if (tid == 0) {
        float l0 = lambdas[0]; int u = 1;
        sLam[0] = l0;
        #pragma unroll
        for (int n = 1; n < NF; n++) { float v = lambdas[n]; sLam[n] = v; u &= (v == l0); }
        sUni = u;
    }
    __syncthreads();
    const bool uniform = (sUni != 0);
    const float lam0 = sLam[0];
    if (!uniform) {
        for (int idx = tid; idx < NF * NDIM; idx += 128) sW[idx] = Wk[idx];
        __syncthreads();
    }

    const int w = tid >> 5, lane = tid & 31;
    const int g = lane >> 2, t4 = lane & 3;
    const u32 kh = smem_u32(sKH), kl = smem_u32(sKL);
    const u32 vh = smem_u32(sVH), vl = smem_u32(sVL);

    float acc[8][4];
    #pragma unroll
    for (int j = 0; j < 8; j++)
        #pragma unroll
        for (int c = 0; c < 4; c++) acc[j][c] = 0.f;

    const long base = ((long)bh * NS + (long)chunk * SCHUNK) * ND;

    for (int t = 0; t < SCHUNK / 64; t++) {
        const long tb = base + (long)t * 64 * ND;
        if (!uniform) {
            route_rows<128>(Kt, Kp, tb, sW, sLam, sLamRow, 64, tid);
            __syncthreads();
        }
        // ---- stage (transposed, bf16 hi/lo) ----
        {
            const int q = tid & 15;       // d-quad
            const int pb = tid >> 4;      // s-pair base 0..7
            #pragma unroll
            for (int it = 0; it < 4; it++) {
                const int p = pb + it * 8;     // s-pair 0..31
                const int s0 = 2 * p;
                const float l0r = uniform ? lam0 : sLamRow[s0];
                const float l1r = uniform ? lam0 : sLamRow[s0 + 1];
                float4 ka = *(const float4*)(Kt + tb + (long)s0 * ND + 4 * q);
                float4 kb = *(const float4*)(Kt + tb + (long)(s0 + 1) * ND + 4 * q);
                float4 pa = *(const float4*)(Kp + tb + (long)s0 * ND + 4 * q);
                float4 pb2 = *(const float4*)(Kp + tb + (long)(s0 + 1) * ND + 4 * q);
                float d0[4] = {ka.x - l0r * pa.x, ka.y - l0r * pa.y,
                               ka.z - l0r * pa.z, ka.w - l0r * pa.w};
                float d1[4] = {kb.x - l1r * pb2.x, kb.y - l1r * pb2.y,
                               kb.z - l1r * pb2.z, kb.w - l1r * pb2.w};
                #pragma unroll
                for (int i = 0; i < 4; i++) {
                    u32 hi, lo; split2(d0[i], d1[i], hi, lo);
                    u32 off = swoff(4 * q + i, s0);
                    *(u32*)(sKH + off) = hi;
                    *(u32*)(sKL + off) = lo;
                }
                float4 va = *(const float4*)(Vg + tb + (long)s0 * ND + 4 * q);
                float4 vb = *(const float4*)(Vg + tb + (long)(s0 + 1) * ND + 4 * q);
                float e0[4] = {va.x, va.y, va.z, va.w};
                float e1[4] = {vb.x, vb.y, vb.z, vb.w};
                #pragma unroll
                for (int i = 0; i < 4; i++) {
                    u32 hi, lo; split2(e0[i], e1[i], hi, lo);
                    u32 off = swoff(4 * q + i, s0);
                    *(u32*)(sVH + off) = hi;
                    *(u32*)(sVL + off) = lo;
                }
            }
        }
        __syncthreads();
        // ---- compute: warp w covers d rows [16w,16w+16), all 64 e ----
        #pragma unroll
        for (int kk = 0; kk < 4; kk++) {
            const int k0 = 16 * kk;
            u32 aH[4], aL[4];
            u32 aoff = swoff(16 * w + (lane & 15), k0 + 8 * (lane >> 4));
            ldsm_x4(aH, kh + aoff);
            ldsm_x4(aL, kl + aoff);
            #pragma unroll
            for (int j = 0; j < 8; j++) {
                u32 boff = swoff(8 * j + (lane & 7), k0 + 8 * ((lane >> 3) & 1));
                u32 bH0, bH1, bL0, bL1;
                ldsm_x2(bH0, bH1, vh + boff);
                ldsm_x2(bL0, bL1, vl + boff);
                mma16816(acc[j], aH, bH0, bH1);
                mma16816(acc[j], aH, bL0, bL1);
                mma16816(acc[j], aL, bH0, bH1);
            }
        }
        __syncthreads();
    }

    float* out = g_KVpart + ((long)chunk * NBH + bh) * (ND * ND);
    #pragma unroll
    for (int j = 0; j < 8; j++) {
        const int r0 = 16 * w + g, e0 = 8 * j + 2 * t4;
        *(float2*)(out + r0 * ND + e0) = make_float2(acc[j][0], acc[j][1]);
        *(float2*)(out + (r0 + 8) * ND + e0) = make_float2(acc[j][2], acc[j][3]);
    }
}

// ==================== Reduce partials -> g_KV ====================
__global__ void __launch_bounds__(256) reduce_kernel()
{
    const int idx = blockIdx.x * 256 + threadIdx.x;
    float s = 0.f;
    #pragma unroll
    for (int c = 0; c < SCHUNKS; c++)
        s += g_KVpart[(long)c * (NBH * ND * ND) + idx];
    g_KV[idx] = s;
}

// ==================== Phase B: O = Qd @ KV via mma.sync ====================
// Per block (st, bh): M=128 s-rows, N=64, K=64. 256 threads (8 warps, m16 each).
// dynamic smem layout (bytes):
#define PB_QH 0
#define PB_QL 16384
#define PB_BH 32768
#define PB_BL 40960
#define PB_W  49152
#define PB_LR 53760
#define PB_LM 54272
#define PB_UN 54336
#define PB_TOTAL 54400

__global__ void __launch_bounds__(256) out_tc(
    const float* __restrict__ Qt, const float* __restrict__ Qp,
    const float* __restrict__ lambdas, const float* __restrict__ Wq,
    float* __restrict__ O)
{
    extern __shared__ char smem[];
    char* sQH = smem + PB_QH;
    char* sQL = smem + PB_QL;
    char* sBH = smem + PB_BH;
    char* sBL = smem + PB_BL;
    float* sW = (float*)(smem + PB_W);
    float* sLamRow = (float*)(smem + PB_LR);
    float* sLam = (float*)(smem + PB_LM);
    int* sUni = (int*)(smem + PB_UN);

    const int tid = threadIdx.x;
    const int st = blockIdx.x, bh = blockIdx.y;

    if (tid == 0) {
        float l0 = lambdas[0]; int u = 1;
        sLam[0] = l0;
        #pragma unroll
        for (int n = 1; n < NF; n++) { float v = lambdas[n]; sLam[n] = v; u &= (v == l0); }
        *sUni = u;
    }
    __syncthreads();
    const bool uniform = (*sUni != 0);
    const float lam0 = sLam[0];

    const long tb = ((long)bh * NS + (long)st * 128) * ND;

    // ---- stage KV (transposed [e][d], bf16 hi/lo); L2-resident (1MB total) ----
    {
        const float* kv = g_KV + (long)bh * ND * ND;
        #pragma unroll
        for (int idx = tid; idx < 2048; idx += 256) {
            const int e = idx & 63, p = idx >> 6;       // d-pair p
            float v0 = kv[(2 * p) * ND + e];
            float v1 = kv[(2 * p + 1) * ND + e];
            u32 hi, lo; split2(v0, v1, hi, lo);
            u32 off = swoff(e, 2 * p);
            *(u32*)(sBH + off) = hi;
            *(u32*)(sBL + off) = lo;
        }
    }

    if (!uniform) {
        for (int idx = tid; idx < NF * NDIM; idx += 256) sW[idx] = Wq[idx];
        __syncthreads();
        route_rows<256>(Qt, Qp, tb, sW, sLam, sLamRow, 128, tid);
        __syncthreads();
    }

    // ---- stage Q_diff row-major [s][d], bf16 hi/lo ----
    #pragma unroll
    for (int idx = tid; idx < 128 * 16; idx += 256) {
        const int s = idx >> 4, c4 = idx & 15;
        const float l = uniform ? lam0 : sLamRow[s];
        float4 a = *(const float4*)(Qt + tb + (long)s * ND + 4 * c4);
        float4 b = *(const float4*)(Qp + tb + (long)s * ND + 4 * c4);
        float dx = a.x - l * b.x, dy = a.y - l * b.y;
        float dz = a.z - l * b.z, dw = a.w - l * b.w;
        u32 hi0, lo0, hi1, lo1;
        split2(dx, dy, hi0, lo0);
        split2(dz, dw, hi1, lo1);
        u32 o0 = swoff(s, 4 * c4), o1 = swoff(s, 4 * c4 + 2);
        *(u32*)(sQH + o0) = hi0;  *(u32*)(sQH + o1) = hi1;
        *(u32*)(sQL + o0) = lo0;  *(u32*)(sQL + o1) = lo1;
    }
    __syncthreads();

    const int w = tid >> 5, lane = tid & 31;
    const int g = lane >> 2, t4 = lane & 3;
    const u32 qh = smem_u32(sQH), ql = smem_u32(sQL);
    const u32 bhp = smem_u32(sBH), blp = smem_u32(sBL);

    float acc[8][4];
    #pragma unroll
    for (int j = 0; j < 8; j++)
        #pragma unroll
        for (int c = 0; c < 4; c++) acc[j][c] = 0.f;

    #pragma unroll
    for (int kk = 0; kk < 4; kk++) {
        const int k0 = 16 * kk;
        u32 aH[4], aL[4];
        u32 aoff = swoff(16 * w + (lane & 15), k0 + 8 * (lane >> 4));
        ldsm_x4(aH, qh + aoff);
        ldsm_x4(aL, ql + aoff);
        #pragma unroll
        for (int j = 0; j < 8; j++) {
            u32 boff = swoff(8 * j + (lane & 7), k0 + 8 * ((lane >> 3) & 1));
            u32 bH0, bH1, bL0, bL1;
            ldsm_x2(bH0, bH1, bhp + boff);
            ldsm_x2(bL0, bL1, blp + boff);
            mma16816(acc[j], aH, bH0, bH1);
            mma16816(acc[j], aH, bL0, bL1);
            mma16816(acc[j], aL, bH0, bH1);
        }
    }

    // ---- epilogue: write O ----
    float* out = O + tb;
    #pragma unroll
    for (int j = 0; j < 8; j++) {
        const int r0 = 16 * w + g, e0 = 8 * j + 2 * t4;
        *(float2*)(out + (long)r0 * ND + e0) = make_float2(acc[j][0], acc[j][1]);
        *(float2*)(out + (long)(r0 + 8) * ND + e0) = make_float2(acc[j][2], acc[j][3]);
    }
}

extern "C" void kernel_launch(void* const* d_in, const int* in_sizes, int n_in,
                              void* d_out, int out_size)
{
    const float* Qt  = (const float*)d_in[0];
    const float* Qp  = (const float*)d_in[1];
    const float* Kt  = (const float*)d_in[2];
    const float* Kp  = (const float*)d_in[3];
    const float* Vg  = (const float*)d_in[4];
    const float* lam = (const float*)d_in[5];
    const float* Wq  = (const float*)d_in[6];
    const float* Wk  = (const float*)d_in[7];
    float* O = (float*)d_out;

    static bool attr_set = false;
    if (!attr_set) {
        cudaFuncSetAttribute(out_tc, cudaFuncAttributeMaxDynamicSharedMemorySize, PB_TOTAL);
        attr_set = true;
    }

    kv_tc<<<dim3(SCHUNKS, NBH), 128>>>(Kt, Kp, Vg, lam, Wk);
    reduce_kernel<<<(NBH * ND * ND) / 256, 256>>>();
    out_tc<<<dim3(NS / 128, NBH), 256, PB_TOTAL>>>(Qt, Qp, lam, Wq, O);
}